// round 2
// baseline (speedup 1.0000x reference)
#include <cuda_runtime.h>
#include <math.h>

#define N_NODES 100000
#define N_EDGES 3200000
#define F_IN    256
#define F_HID   16
#define F_OUT   40

// Scratch (static __device__ — no allocations allowed)
__device__ float g_hs [N_NODES * F_HID];   // dinv-prescaled features (scatter source)
__device__ float g_agg[N_NODES * F_HID];   // aggregation accumulator
__device__ float g_dinv[N_NODES];
__device__ int   g_deg [N_NODES];
__device__ int   g_is64;

// ---------------------------------------------------------------------------
// Edge-index dtype detection: int64 data has all of the first 64 values in
// [0, N_NODES); int32 data reinterpreted as int64 packs two random int32 per
// value -> out of range with overwhelming probability. Deterministic.
// ---------------------------------------------------------------------------
__global__ void k_detect(const long long* __restrict__ ei) {
    if (threadIdx.x == 0) {
        int ok = 1;
        for (int i = 0; i < 64; i++) {
            long long v = ei[i];
            if (v < 0 || v >= (long long)N_NODES) ok = 0;
        }
        g_is64 = ok;
    }
}

__device__ __forceinline__ int edge_at(const void* ei, int is64, long long pos) {
    if (is64) return (int)((const long long*)ei)[pos];
    return ((const int*)ei)[pos];
}

// ---------------------------------------------------------------------------
// Degree (self-loop => init 1), then dinv = deg^-1/2
// ---------------------------------------------------------------------------
__global__ void k_deg_init() {
    int i = blockIdx.x * 256 + threadIdx.x;
    if (i < N_NODES) g_deg[i] = 1;
}

__global__ void k_deg_scatter(const void* __restrict__ ei) {
    int is64 = g_is64;
    int stride = gridDim.x * 256;
    for (int e = blockIdx.x * 256 + threadIdx.x; e < N_EDGES; e += stride) {
        int d = edge_at(ei, is64, (long long)N_EDGES + e);
        atomicAdd(&g_deg[d], 1);
    }
}

__global__ void k_dinv() {
    int i = blockIdx.x * 256 + threadIdx.x;
    if (i < N_NODES) g_dinv[i] = rsqrtf((float)g_deg[i]);
}

// ---------------------------------------------------------------------------
// Layer-1 GEMM: hs[i,:] = dinv[i] * (x[i,:] @ W1), also seeds agg with the
// self-loop contribution (agg init = hs).
// One thread per node; x staged through shared in 16-col chunks (17-padded ->
// conflict-free LDS); W1 rows read as broadcast LDS.128.
// ---------------------------------------------------------------------------
__global__ void k_gemm1(const float* __restrict__ x, const float* __restrict__ W1) {
    __shared__ float W1s[F_IN * F_HID];      // 16 KB
    __shared__ float xs[256][17];            // 17.4 KB, padded
    int tid = threadIdx.x;
    for (int i = tid; i < F_IN * F_HID; i += 256) W1s[i] = W1[i];

    int node0 = blockIdx.x * 256;
    int node  = node0 + tid;
    float acc[F_HID];
#pragma unroll
    for (int j = 0; j < F_HID; j++) acc[j] = 0.f;
    __syncthreads();

    for (int kc = 0; kc < F_IN; kc += 16) {
        // stage 256 nodes x 16 cols, coalesced float4 loads
#pragma unroll
        for (int r = 0; r < 4; r++) {
            int i  = tid + r * 256;
            int n  = i >> 2, c4 = i & 3;
            float4 v = make_float4(0.f, 0.f, 0.f, 0.f);
            if (node0 + n < N_NODES)
                v = *(const float4*)(x + (size_t)(node0 + n) * F_IN + kc + c4 * 4);
            xs[n][c4 * 4 + 0] = v.x; xs[n][c4 * 4 + 1] = v.y;
            xs[n][c4 * 4 + 2] = v.z; xs[n][c4 * 4 + 3] = v.w;
        }
        __syncthreads();
#pragma unroll
        for (int c = 0; c < 16; c++) {
            float xv = xs[tid][c];
            const float4* wr = (const float4*)(W1s + (kc + c) * F_HID);
            float4 w0 = wr[0], w1 = wr[1], w2 = wr[2], w3 = wr[3];
            acc[0]  = fmaf(xv, w0.x, acc[0]);  acc[1]  = fmaf(xv, w0.y, acc[1]);
            acc[2]  = fmaf(xv, w0.z, acc[2]);  acc[3]  = fmaf(xv, w0.w, acc[3]);
            acc[4]  = fmaf(xv, w1.x, acc[4]);  acc[5]  = fmaf(xv, w1.y, acc[5]);
            acc[6]  = fmaf(xv, w1.z, acc[6]);  acc[7]  = fmaf(xv, w1.w, acc[7]);
            acc[8]  = fmaf(xv, w2.x, acc[8]);  acc[9]  = fmaf(xv, w2.y, acc[9]);
            acc[10] = fmaf(xv, w2.z, acc[10]); acc[11] = fmaf(xv, w2.w, acc[11]);
            acc[12] = fmaf(xv, w3.x, acc[12]); acc[13] = fmaf(xv, w3.y, acc[13]);
            acc[14] = fmaf(xv, w3.z, acc[14]); acc[15] = fmaf(xv, w3.w, acc[15]);
        }
        __syncthreads();
    }

    if (node < N_NODES) {
        float di = g_dinv[node];
#pragma unroll
        for (int j = 0; j < F_HID; j++) {
            float v = di * acc[j];
            g_hs [node * F_HID + j] = v;
            g_agg[node * F_HID + j] = v;   // self-loop seed
        }
    }
}

// ---------------------------------------------------------------------------
// Edge scatter: agg[dst] += hs[src]  (dinv[dst] factored out, applied later).
// 16 floats per edge via four red.global.add.v4.f32 (sm_90+ vector atomics).
// Grid-stride: 2 edges/thread improves index-load MLP and halves grid size.
// ---------------------------------------------------------------------------
__device__ __forceinline__ void red4(float* p, float4 v) {
    asm volatile("red.global.add.v4.f32 [%0], {%1, %2, %3, %4};"
                 :: "l"(p), "f"(v.x), "f"(v.y), "f"(v.z), "f"(v.w)
                 : "memory");
}

__global__ void k_scatter(const void* __restrict__ ei) {
    int is64 = g_is64;
    int stride = gridDim.x * 256;
    for (int e = blockIdx.x * 256 + threadIdx.x; e < N_EDGES; e += stride) {
        int s = edge_at(ei, is64, e);
        int d = edge_at(ei, is64, (long long)N_EDGES + e);
        const float4* hp = (const float4*)(g_hs + (size_t)s * F_HID);
        float4 v0 = hp[0], v1 = hp[1], v2 = hp[2], v3 = hp[3];
        float* ap = g_agg + (size_t)d * F_HID;
        red4(ap + 0,  v0);
        red4(ap + 4,  v1);
        red4(ap + 8,  v2);
        red4(ap + 12, v3);
    }
}

// ---------------------------------------------------------------------------
// Between layers: h = relu(dinv*agg + b1); hs2 = dinv*h; re-seed agg = hs2.
// ---------------------------------------------------------------------------
__global__ void k_mid(const float* __restrict__ b1) {
    int idx = blockIdx.x * 256 + threadIdx.x;
    if (idx >= N_NODES * F_HID) return;
    int node = idx >> 4, j = idx & 15;
    float di = g_dinv[node];
    float v  = fmaf(di, g_agg[idx], b1[j]);
    v = fmaxf(v, 0.f) * di;
    g_hs[idx]  = v;
    g_agg[idx] = v;   // self-loop seed for layer 2
}

// ---------------------------------------------------------------------------
// Final: logits = (dinv[i]*agg2[i,:]) @ W2 + b2, then log_softmax over 40.
// One thread per node; W2/b2 broadcast from shared (LDS.128).
// ---------------------------------------------------------------------------
__global__ void k_final(const float* __restrict__ W2, const float* __restrict__ b2,
                        float* __restrict__ out) {
    __shared__ float W2s[F_HID * F_OUT];
    __shared__ float b2s[F_OUT];
    int tid = threadIdx.x;
    for (int i = tid; i < F_HID * F_OUT; i += 256) W2s[i] = W2[i];
    if (tid < F_OUT) b2s[tid] = b2[tid];
    __syncthreads();

    int i = blockIdx.x * 256 + tid;
    if (i >= N_NODES) return;

    float di = g_dinv[i];
    float a[F_HID];
    const float4* ap = (const float4*)(g_agg + (size_t)i * F_HID);
#pragma unroll
    for (int q = 0; q < 4; q++) {
        float4 v = ap[q];
        a[q * 4 + 0] = di * v.x; a[q * 4 + 1] = di * v.y;
        a[q * 4 + 2] = di * v.z; a[q * 4 + 3] = di * v.w;
    }

    float l[F_OUT];
#pragma unroll
    for (int j = 0; j < F_OUT; j++) l[j] = b2s[j];
#pragma unroll
    for (int k = 0; k < F_HID; k++) {
        float av = a[k];
#pragma unroll
        for (int q = 0; q < F_OUT / 4; q++) {
            float4 w = *(const float4*)(W2s + k * F_OUT + q * 4);
            l[q * 4 + 0] = fmaf(av, w.x, l[q * 4 + 0]);
            l[q * 4 + 1] = fmaf(av, w.y, l[q * 4 + 1]);
            l[q * 4 + 2] = fmaf(av, w.z, l[q * 4 + 2]);
            l[q * 4 + 3] = fmaf(av, w.w, l[q * 4 + 3]);
        }
    }

    float m = l[0];
#pragma unroll
    for (int j = 1; j < F_OUT; j++) m = fmaxf(m, l[j]);
    float ssum = 0.f;
#pragma unroll
    for (int j = 0; j < F_OUT; j++) ssum += expf(l[j] - m);
    float lse = m + logf(ssum);

    float* op = out + (size_t)i * F_OUT;
#pragma unroll
    for (int j = 0; j < F_OUT; j++) op[j] = l[j] - lse;
}

// ---------------------------------------------------------------------------
extern "C" void kernel_launch(void* const* d_in, const int* in_sizes, int n_in,
                              void* d_out, int out_size) {
    const float* x  = (const float*)d_in[0];
    const void*  ei = d_in[1];
    const float* W1 = (const float*)d_in[2];
    const float* b1 = (const float*)d_in[3];
    const float* W2 = (const float*)d_in[4];
    const float* b2 = (const float*)d_in[5];
    float* out = (float*)d_out;

    const int nbN = (N_NODES + 255) / 256;          // 391
    const int nbE = 6250;                           // 2 edges/thread, grid-stride
    const int nbF = (N_NODES * F_HID + 255) / 256;  // 6250

    k_detect<<<1, 32>>>((const long long*)ei);
    k_deg_init<<<nbN, 256>>>();
    k_deg_scatter<<<nbE, 256>>>(ei);
    k_dinv<<<nbN, 256>>>();
    k_gemm1<<<nbN, 256>>>(x, W1);
    k_scatter<<<nbE, 256>>>(ei);       // layer-1 aggregation
    k_mid<<<nbF, 256>>>(b1);
    k_scatter<<<nbE, 256>>>(ei);       // layer-2 aggregation (16-wide thanks to commuting W2)
    k_final<<<nbN, 256>>>(W2, b2, out);
}

// round 3
// speedup vs baseline: 1.3111x; 1.3111x over previous
#include <cuda_runtime.h>
#include <math.h>

#define N_NODES 100000
#define N_EDGES 3200000
#define F_IN    256
#define F_HID   16
#define F_OUT   40
#define NB_SCAN 98            // ceil(100000/1024)

// ---- static scratch (no allocations allowed) ----
__device__ float g_hs  [N_NODES * F_HID];  // pass-1 gather source (dinv * xW1)
__device__ float g_hs2 [N_NODES * F_HID];  // pass-2 gather source
__device__ float g_dinv[N_NODES];
__device__ int   g_cnt [N_NODES];          // in-degree (excl. self-loop)
__device__ int   g_fill[N_NODES];          // fill cursor for CSR build
__device__ int   g_rowp[N_NODES];          // block-local exclusive prefix of cnt
__device__ int   g_aux [128];              // per-scan-block exclusive offsets
__device__ int   g_csr [N_EDGES];          // src ids grouped by dst
__device__ int   g_is64;

// ---------------------------------------------------------------------------
// Zero counters + edge-index dtype detection.
// int64 data: first 64 values all in [0, N_NODES). int32 data reinterpreted
// as int64 packs two random int32 per value -> out of range w.h.p.
// ---------------------------------------------------------------------------
__global__ void k_zero_detect(const long long* __restrict__ ei) {
    int i = blockIdx.x * 1024 + threadIdx.x;
    if (i < N_NODES)              g_cnt [i]           = 0;
    else if (i < 2 * N_NODES)     g_fill[i - N_NODES] = 0;
    if (blockIdx.x == 0 && threadIdx.x == 0) {
        int ok = 1;
        for (int j = 0; j < 64; j++) {
            long long v = ei[j];
            if (v < 0 || v >= (long long)N_NODES) ok = 0;
        }
        g_is64 = ok;
    }
}

__device__ __forceinline__ int edge_at(const void* ei, int is64, long long pos) {
    if (is64) return (int)((const long long*)ei)[pos];
    return ((const int*)ei)[pos];
}

// ---------------------------------------------------------------------------
// In-degree count (scalar int atomics, spread addresses -> near LSU floor)
// ---------------------------------------------------------------------------
__global__ void k_count(const void* __restrict__ ei) {
    int is64 = g_is64;
    int stride = gridDim.x * 256;
    for (int e = blockIdx.x * 256 + threadIdx.x; e < N_EDGES; e += stride) {
        int d = edge_at(ei, is64, (long long)N_EDGES + e);
        atomicAdd(&g_cnt[d], 1);
    }
}

// ---------------------------------------------------------------------------
// Scan stage 1: block-local exclusive prefix over cnt (1024/block),
// block totals -> aux. Also computes dinv = rsqrt(cnt+1) (self-loop).
// ---------------------------------------------------------------------------
__global__ void k_scan1() {
    __shared__ int sh[1024];
    int tid = threadIdx.x;
    int gid = blockIdx.x * 1024 + tid;
    int v = (gid < N_NODES) ? g_cnt[gid] : 0;
    sh[tid] = v;
    __syncthreads();
#pragma unroll
    for (int off = 1; off < 1024; off <<= 1) {
        int t = (tid >= off) ? sh[tid - off] : 0;
        __syncthreads();
        sh[tid] += t;
        __syncthreads();
    }
    if (gid < N_NODES) {
        g_rowp[gid] = sh[tid] - v;          // exclusive within block
        g_dinv[gid] = rsqrtf((float)(v + 1));
    }
    if (tid == 1023) g_aux[blockIdx.x] = sh[1023];
}

// Scan stage 2: exclusive scan over the 98 block totals (single block).
__global__ void k_scan2() {
    __shared__ int sh[128];
    int tid = threadIdx.x;
    int v = (tid < NB_SCAN) ? g_aux[tid] : 0;
    sh[tid] = v;
    __syncthreads();
#pragma unroll
    for (int off = 1; off < 128; off <<= 1) {
        int t = (tid >= off) ? sh[tid - off] : 0;
        __syncthreads();
        sh[tid] += t;
        __syncthreads();
    }
    if (tid < NB_SCAN) g_aux[tid] = sh[tid] - v;   // exclusive
}

// ---------------------------------------------------------------------------
// CSR fill: csr[rowptr[d] + cursor++] = src
// ---------------------------------------------------------------------------
__global__ void k_fill(const void* __restrict__ ei) {
    int is64 = g_is64;
    int stride = gridDim.x * 256;
    for (int e = blockIdx.x * 256 + threadIdx.x; e < N_EDGES; e += stride) {
        int s = edge_at(ei, is64, e);
        int d = edge_at(ei, is64, (long long)N_EDGES + e);
        int base = g_rowp[d] + g_aux[d >> 10];
        int off  = atomicAdd(&g_fill[d], 1);
        g_csr[base + off] = s;
    }
}

// ---------------------------------------------------------------------------
// Layer-1 GEMM: hs[i,:] = dinv[i] * (x[i,:] @ W1).
// One thread per node; x staged through shared (17-padded), W1 broadcast LDS.
// ---------------------------------------------------------------------------
__global__ void k_gemm1(const float* __restrict__ x, const float* __restrict__ W1) {
    __shared__ float W1s[F_IN * F_HID];      // 16 KB
    __shared__ float xs[256][17];            // 17.4 KB, padded
    int tid = threadIdx.x;
    for (int i = tid; i < F_IN * F_HID; i += 256) W1s[i] = W1[i];

    int node0 = blockIdx.x * 256;
    int node  = node0 + tid;
    float acc[F_HID];
#pragma unroll
    for (int j = 0; j < F_HID; j++) acc[j] = 0.f;
    __syncthreads();

    for (int kc = 0; kc < F_IN; kc += 16) {
#pragma unroll
        for (int r = 0; r < 4; r++) {
            int i  = tid + r * 256;
            int n  = i >> 2, c4 = i & 3;
            float4 v = make_float4(0.f, 0.f, 0.f, 0.f);
            if (node0 + n < N_NODES)
                v = *(const float4*)(x + (size_t)(node0 + n) * F_IN + kc + c4 * 4);
            xs[n][c4 * 4 + 0] = v.x; xs[n][c4 * 4 + 1] = v.y;
            xs[n][c4 * 4 + 2] = v.z; xs[n][c4 * 4 + 3] = v.w;
        }
        __syncthreads();
#pragma unroll
        for (int c = 0; c < 16; c++) {
            float xv = xs[tid][c];
            const float4* wr = (const float4*)(W1s + (kc + c) * F_HID);
            float4 w0 = wr[0], w1 = wr[1], w2 = wr[2], w3 = wr[3];
            acc[0]  = fmaf(xv, w0.x, acc[0]);  acc[1]  = fmaf(xv, w0.y, acc[1]);
            acc[2]  = fmaf(xv, w0.z, acc[2]);  acc[3]  = fmaf(xv, w0.w, acc[3]);
            acc[4]  = fmaf(xv, w1.x, acc[4]);  acc[5]  = fmaf(xv, w1.y, acc[5]);
            acc[6]  = fmaf(xv, w1.z, acc[6]);  acc[7]  = fmaf(xv, w1.w, acc[7]);
            acc[8]  = fmaf(xv, w2.x, acc[8]);  acc[9]  = fmaf(xv, w2.y, acc[9]);
            acc[10] = fmaf(xv, w2.z, acc[10]); acc[11] = fmaf(xv, w2.w, acc[11]);
            acc[12] = fmaf(xv, w3.x, acc[12]); acc[13] = fmaf(xv, w3.y, acc[13]);
            acc[14] = fmaf(xv, w3.z, acc[14]); acc[15] = fmaf(xv, w3.w, acc[15]);
        }
        __syncthreads();
    }

    if (node < N_NODES) {
        float di = g_dinv[node];
#pragma unroll
        for (int j = 0; j < F_HID; j++)
            g_hs[node * F_HID + j] = di * acc[j];
    }
}

// ---------------------------------------------------------------------------
// Gather pass 1 (warp per node): sum hs[src] over incoming edges + self,
// then fused mid: hs2 = dinv * relu(dinv*total + b1).
// Lane layout: group g = lane>>4 handles alternating edges; feature f = lane&15.
// ---------------------------------------------------------------------------
__global__ void k_gather1(const float* __restrict__ b1) {
    int lane = threadIdx.x & 31;
    int n = blockIdx.x * 8 + (threadIdx.x >> 5);
    if (n >= N_NODES) return;

    int g = lane >> 4;
    int f = lane & 15;
    int rs = g_rowp[n] + g_aux[n >> 10];
    int re = rs + g_cnt[n];

    float acc = 0.f;
    for (int base = rs; base < re; base += 8) {
#pragma unroll
        for (int u = 0; u < 4; u++) {
            int idx = base + 2 * u + g;
            if (idx < re) {
                int s = g_csr[idx];
                acc += g_hs[(size_t)s * F_HID + f];
            }
        }
    }
    acc += __shfl_xor_sync(0xffffffffu, acc, 16);   // all lanes: full sum for feature f

    float di = g_dinv[n];
    float total = acc + g_hs[(size_t)n * F_HID + f];          // self-loop
    float v = fmaxf(fmaf(di, total, b1[f]), 0.f) * di;        // relu + prescale
    if (lane < 16) g_hs2[(size_t)n * F_HID + f] = v;
}

// ---------------------------------------------------------------------------
// Gather pass 2 fused with GEMM2 + log_softmax (warp per node).
// a[f] = dinv * (sum hs2[src] + hs2[n]); logits j = sum_k a[k]*W2[k][j] + b2[j];
// 40 outputs over 32 lanes (lane<8 handles a second output).
// ---------------------------------------------------------------------------
__global__ void k_gather2_final(const float* __restrict__ W2,
                                const float* __restrict__ b2,
                                float* __restrict__ out) {
    __shared__ float W2s[F_HID * F_OUT];
    __shared__ float b2s[F_OUT];
    int tid = threadIdx.x;
    for (int i = tid; i < F_HID * F_OUT; i += 256) W2s[i] = W2[i];
    if (tid < F_OUT) b2s[tid] = b2[tid];
    __syncthreads();

    int lane = tid & 31;
    int n = blockIdx.x * 8 + (tid >> 5);
    if (n >= N_NODES) return;

    int g = lane >> 4;
    int f = lane & 15;
    int rs = g_rowp[n] + g_aux[n >> 10];
    int re = rs + g_cnt[n];

    float acc = 0.f;
    for (int base = rs; base < re; base += 8) {
#pragma unroll
        for (int u = 0; u < 4; u++) {
            int idx = base + 2 * u + g;
            if (idx < re) {
                int s = g_csr[idx];
                acc += g_hs2[(size_t)s * F_HID + f];
            }
        }
    }
    acc += __shfl_xor_sync(0xffffffffu, acc, 16);

    float aval = g_dinv[n] * (acc + g_hs2[(size_t)n * F_HID + f]); // feature f, all lanes

    // logits: lane handles jA = lane; lanes 0-7 also jB = lane + 32
    int jA = lane, jB = lane + 32;
    float l0 = b2s[jA];
    float l1 = (jB < F_OUT) ? b2s[jB] : -3.0e38f;
#pragma unroll
    for (int k = 0; k < F_HID; k++) {
        float ak = __shfl_sync(0xffffffffu, aval, k);  // lane k holds feature k
        l0 = fmaf(ak, W2s[k * F_OUT + jA], l0);
        if (jB < F_OUT) l1 = fmaf(ak, W2s[k * F_OUT + jB], l1);
    }

    // log_softmax over 40 values spread across the warp
    float m = fmaxf(l0, l1);
#pragma unroll
    for (int off = 16; off > 0; off >>= 1)
        m = fmaxf(m, __shfl_xor_sync(0xffffffffu, m, off));
    float s = expf(l0 - m) + ((jB < F_OUT) ? expf(l1 - m) : 0.f);
#pragma unroll
    for (int off = 16; off > 0; off >>= 1)
        s += __shfl_xor_sync(0xffffffffu, s, off);
    float lse = m + logf(s);

    float* op = out + (size_t)n * F_OUT;
    op[jA] = l0 - lse;
    if (jB < F_OUT) op[jB] = l1 - lse;
}

// ---------------------------------------------------------------------------
extern "C" void kernel_launch(void* const* d_in, const int* in_sizes, int n_in,
                              void* d_out, int out_size) {
    const float* x  = (const float*)d_in[0];
    const void*  ei = d_in[1];
    const float* W1 = (const float*)d_in[2];
    const float* b1 = (const float*)d_in[3];
    const float* W2 = (const float*)d_in[4];
    const float* b2 = (const float*)d_in[5];
    float* out = (float*)d_out;

    k_zero_detect<<<196, 1024>>>((const long long*)ei);
    k_count<<<6250, 256>>>(ei);
    k_scan1<<<NB_SCAN, 1024>>>();
    k_scan2<<<1, 128>>>();
    k_fill<<<6250, 256>>>(ei);
    k_gemm1<<<(N_NODES + 255) / 256, 256>>>(x, W1);
    k_gather1<<<(N_NODES + 7) / 8, 256>>>(b1);
    k_gather2_final<<<(N_NODES + 7) / 8, 256>>>(W2, b2, out);
}

// round 4
// speedup vs baseline: 1.3971x; 1.0656x over previous
#include <cuda_runtime.h>
#include <math.h>

#define N_NODES 100000
#define N_EDGES 3200000
#define F_IN    256
#define F_HID   16
#define F_OUT   40

// ---- static scratch (no allocations allowed) ----
__device__ float g_hs  [N_NODES * F_HID];  // pass-1 gather source (dinv * xW1)
__device__ float g_hs2 [N_NODES * F_HID];  // pass-2 gather source
__device__ float g_dinv[N_NODES];
__device__ int   g_cnt [N_NODES];          // in-degree (excl. self-loop)
__device__ int   g_fill[N_NODES];          // fill cursor for CSR build
__device__ int   g_rowp[N_NODES];          // absolute row start in g_csr
__device__ int   g_csr [N_EDGES];          // src ids grouped by dst
__device__ int   g_base;                   // global CSR offset counter
__device__ int   g_is64;

// ---------------------------------------------------------------------------
// Zero counters + edge-index dtype detection.
// int64 data: first 64 values all in [0, N_NODES). int32 data reinterpreted
// as int64 packs two random int32 per value -> out of range w.h.p.
// ---------------------------------------------------------------------------
__global__ void k_zero_detect(const long long* __restrict__ ei) {
    int i = blockIdx.x * 1024 + threadIdx.x;
    if (i < N_NODES)              g_cnt [i]           = 0;
    else if (i < 2 * N_NODES)     g_fill[i - N_NODES] = 0;
    if (blockIdx.x == 0 && threadIdx.x == 0) {
        g_base = 0;
        int ok = 1;
        for (int j = 0; j < 64; j++) {
            long long v = ei[j];
            if (v < 0 || v >= (long long)N_NODES) ok = 0;
        }
        g_is64 = ok;
    }
}

__device__ __forceinline__ int edge_at(const void* ei, int is64, long long pos) {
    if (is64) return (int)((const long long*)ei)[pos];
    return ((const int*)ei)[pos];
}

// ---------------------------------------------------------------------------
// In-degree count (scalar int atomics, spread addresses -> near LSU floor)
// ---------------------------------------------------------------------------
__global__ void k_count(const void* __restrict__ ei) {
    int is64 = g_is64;
    int stride = gridDim.x * 256;
    for (int e = blockIdx.x * 256 + threadIdx.x; e < N_EDGES; e += stride) {
        int d = edge_at(ei, is64, (long long)N_EDGES + e);
        atomicAdd(&g_cnt[d], 1);
    }
}

// ---------------------------------------------------------------------------
// Single-kernel exclusive scan: warp-shuffle scan within block (1024 thr),
// block base via atomicAdd on g_base (order nondeterministic -> only permutes
// CSR row placement -> fp32 sum order; within tolerance).
// Also computes dinv = rsqrt(cnt+1) (self-loop).
// ---------------------------------------------------------------------------
__global__ void k_scan() {
    __shared__ int wtot[32];
    __shared__ int sbase;
    int tid  = threadIdx.x;
    int lane = tid & 31, wid = tid >> 5;
    int gid  = blockIdx.x * 1024 + tid;

    int v = (gid < N_NODES) ? g_cnt[gid] : 0;
    int x = v;
#pragma unroll
    for (int off = 1; off < 32; off <<= 1) {
        int t = __shfl_up_sync(0xffffffffu, x, off);
        if (lane >= off) x += t;
    }
    if (lane == 31) wtot[wid] = x;
    __syncthreads();
    if (wid == 0) {
        int w = wtot[lane];
        int y = w;
#pragma unroll
        for (int off = 1; off < 32; off <<= 1) {
            int t = __shfl_up_sync(0xffffffffu, y, off);
            if (lane >= off) y += t;
        }
        wtot[lane] = y - w;                       // exclusive warp offsets
        if (lane == 31) sbase = atomicAdd(&g_base, y);  // block total -> base
    }
    __syncthreads();
    if (gid < N_NODES) {
        g_rowp[gid] = sbase + wtot[wid] + (x - v);
        g_dinv[gid] = rsqrtf((float)(v + 1));
    }
}

// ---------------------------------------------------------------------------
// CSR fill: csr[rowp[d] + cursor++] = src
// ---------------------------------------------------------------------------
__global__ void k_fill(const void* __restrict__ ei) {
    int is64 = g_is64;
    int stride = gridDim.x * 256;
    for (int e = blockIdx.x * 256 + threadIdx.x; e < N_EDGES; e += stride) {
        int s = edge_at(ei, is64, e);
        int d = edge_at(ei, is64, (long long)N_EDGES + e);
        int off = atomicAdd(&g_fill[d], 1);
        g_csr[g_rowp[d] + off] = s;
    }
}

// ---------------------------------------------------------------------------
// Layer-1 GEMM: hs[i,:] = dinv[i] * (x[i,:] @ W1).
// One thread per node; x staged through shared (17-padded), W1 broadcast LDS.
// ---------------------------------------------------------------------------
__global__ void k_gemm1(const float* __restrict__ x, const float* __restrict__ W1) {
    __shared__ float W1s[F_IN * F_HID];      // 16 KB
    __shared__ float xs[256][17];            // 17.4 KB, padded
    int tid = threadIdx.x;
    for (int i = tid; i < F_IN * F_HID; i += 256) W1s[i] = W1[i];

    int node0 = blockIdx.x * 256;
    int node  = node0 + tid;
    float acc[F_HID];
#pragma unroll
    for (int j = 0; j < F_HID; j++) acc[j] = 0.f;
    __syncthreads();

    for (int kc = 0; kc < F_IN; kc += 16) {
#pragma unroll
        for (int r = 0; r < 4; r++) {
            int i  = tid + r * 256;
            int n  = i >> 2, c4 = i & 3;
            float4 v = make_float4(0.f, 0.f, 0.f, 0.f);
            if (node0 + n < N_NODES)
                v = *(const float4*)(x + (size_t)(node0 + n) * F_IN + kc + c4 * 4);
            xs[n][c4 * 4 + 0] = v.x; xs[n][c4 * 4 + 1] = v.y;
            xs[n][c4 * 4 + 2] = v.z; xs[n][c4 * 4 + 3] = v.w;
        }
        __syncthreads();
#pragma unroll
        for (int c = 0; c < 16; c++) {
            float xv = xs[tid][c];
            const float4* wr = (const float4*)(W1s + (kc + c) * F_HID);
            float4 w0 = wr[0], w1 = wr[1], w2 = wr[2], w3 = wr[3];
            acc[0]  = fmaf(xv, w0.x, acc[0]);  acc[1]  = fmaf(xv, w0.y, acc[1]);
            acc[2]  = fmaf(xv, w0.z, acc[2]);  acc[3]  = fmaf(xv, w0.w, acc[3]);
            acc[4]  = fmaf(xv, w1.x, acc[4]);  acc[5]  = fmaf(xv, w1.y, acc[5]);
            acc[6]  = fmaf(xv, w1.z, acc[6]);  acc[7]  = fmaf(xv, w1.w, acc[7]);
            acc[8]  = fmaf(xv, w2.x, acc[8]);  acc[9]  = fmaf(xv, w2.y, acc[9]);
            acc[10] = fmaf(xv, w2.z, acc[10]); acc[11] = fmaf(xv, w2.w, acc[11]);
            acc[12] = fmaf(xv, w3.x, acc[12]); acc[13] = fmaf(xv, w3.y, acc[13]);
            acc[14] = fmaf(xv, w3.z, acc[14]); acc[15] = fmaf(xv, w3.w, acc[15]);
        }
        __syncthreads();
    }

    if (node < N_NODES) {
        float di = g_dinv[node];
#pragma unroll
        for (int j = 0; j < F_HID; j++)
            g_hs[node * F_HID + j] = di * acc[j];
    }
}

// ---------------------------------------------------------------------------
// Vectorized warp gather: lane l -> edge slot (l>>2), quad q = l&3 loads a
// float4 of the source row. One LDG.128 warp instr covers 8 edges; 2-deep
// unroll keeps ~8 loads in flight. Returns this lane's quad sum (valid in
// ALL lanes after the xor-reduction).
// ---------------------------------------------------------------------------
__device__ __forceinline__ float4 warp_gather(const float4* __restrict__ src4,
                                              const int* __restrict__ csr,
                                              int rs, int re, int eo, int q) {
    float4 a0 = make_float4(0.f, 0.f, 0.f, 0.f);
    float4 a1 = make_float4(0.f, 0.f, 0.f, 0.f);
    for (int base = rs; base < re; base += 16) {
        int i0 = base + eo, i1 = base + 8 + eo;
        if (i0 < re) {
            int s = __ldg(&csr[i0]);
            float4 v = src4[(size_t)s * 4 + q];
            a0.x += v.x; a0.y += v.y; a0.z += v.z; a0.w += v.w;
        }
        if (i1 < re) {
            int s = __ldg(&csr[i1]);
            float4 v = src4[(size_t)s * 4 + q];
            a1.x += v.x; a1.y += v.y; a1.z += v.z; a1.w += v.w;
        }
    }
    a0.x += a1.x; a0.y += a1.y; a0.z += a1.z; a0.w += a1.w;
#pragma unroll
    for (int off = 4; off < 32; off <<= 1) {
        a0.x += __shfl_xor_sync(0xffffffffu, a0.x, off);
        a0.y += __shfl_xor_sync(0xffffffffu, a0.y, off);
        a0.z += __shfl_xor_sync(0xffffffffu, a0.z, off);
        a0.w += __shfl_xor_sync(0xffffffffu, a0.w, off);
    }
    return a0;
}

// ---------------------------------------------------------------------------
// Gather pass 1 + fused mid: hs2 = dinv * relu(dinv*(sum + self) + b1)
// ---------------------------------------------------------------------------
__global__ void k_gather1(const float* __restrict__ b1) {
    int tid = threadIdx.x, lane = tid & 31;
    int n = blockIdx.x * 8 + (tid >> 5);      // grid sized so n < N_NODES always
    int eo = lane >> 2, q = lane & 3;
    int rs = g_rowp[n], re = rs + g_cnt[n];

    float4 a = warp_gather((const float4*)g_hs, g_csr, rs, re, eo, q);

    float4 sv = ((const float4*)g_hs)[(size_t)n * 4 + q];
    float di = g_dinv[n];
    float4 b = *(const float4*)(b1 + q * 4);
    float4 r;
    r.x = fmaxf(fmaf(di, a.x + sv.x, b.x), 0.f) * di;
    r.y = fmaxf(fmaf(di, a.y + sv.y, b.y), 0.f) * di;
    r.z = fmaxf(fmaf(di, a.z + sv.z, b.z), 0.f) * di;
    r.w = fmaxf(fmaf(di, a.w + sv.w, b.w), 0.f) * di;
    if (lane < 4) ((float4*)g_hs2)[(size_t)n * 4 + lane] = r;  // lane l has q=l
}

// ---------------------------------------------------------------------------
// Gather pass 2 fused with GEMM2 + log_softmax (warp per node).
// ---------------------------------------------------------------------------
__global__ void k_gather2_final(const float* __restrict__ W2,
                                const float* __restrict__ b2,
                                float* __restrict__ out) {
    __shared__ float W2s[F_HID * F_OUT];
    __shared__ float b2s[F_OUT];
    int tid = threadIdx.x;
    for (int i = tid; i < F_HID * F_OUT; i += 256) W2s[i] = W2[i];
    if (tid < F_OUT) b2s[tid] = b2[tid];
    __syncthreads();

    int lane = tid & 31;
    int n = blockIdx.x * 8 + (tid >> 5);
    int eo = lane >> 2, q = lane & 3;
    int rs = g_rowp[n], re = rs + g_cnt[n];

    float4 a = warp_gather((const float4*)g_hs2, g_csr, rs, re, eo, q);

    float4 sv = ((const float4*)g_hs2)[(size_t)n * 4 + q];
    float di = g_dinv[n];
    float4 av;                                 // features q*4..q*4+3
    av.x = di * (a.x + sv.x); av.y = di * (a.y + sv.y);
    av.z = di * (a.z + sv.z); av.w = di * (a.w + sv.w);

    // logits: lane handles jA = lane; lanes 0-7 also jB = lane + 32
    int jA = lane, jB = lane + 32;
    float l0 = b2s[jA];
    float l1 = (jB < F_OUT) ? b2s[jB] : -3.0e38f;
#pragma unroll
    for (int kq = 0; kq < 4; kq++) {           // lane kq holds quad kq
        float c0 = __shfl_sync(0xffffffffu, av.x, kq);
        float c1 = __shfl_sync(0xffffffffu, av.y, kq);
        float c2 = __shfl_sync(0xffffffffu, av.z, kq);
        float c3 = __shfl_sync(0xffffffffu, av.w, kq);
        const float* w = W2s + (kq * 4) * F_OUT;
        l0 = fmaf(c0, w[jA],             l0);
        l0 = fmaf(c1, w[F_OUT + jA],     l0);
        l0 = fmaf(c2, w[2 * F_OUT + jA], l0);
        l0 = fmaf(c3, w[3 * F_OUT + jA], l0);
        if (jB < F_OUT) {
            l1 = fmaf(c0, w[jB],             l1);
            l1 = fmaf(c1, w[F_OUT + jB],     l1);
            l1 = fmaf(c2, w[2 * F_OUT + jB], l1);
            l1 = fmaf(c3, w[3 * F_OUT + jB], l1);
        }
    }

    // log_softmax over 40 values spread across the warp
    float m = fmaxf(l0, l1);
#pragma unroll
    for (int off = 16; off > 0; off >>= 1)
        m = fmaxf(m, __shfl_xor_sync(0xffffffffu, m, off));
    float s = expf(l0 - m) + ((jB < F_OUT) ? expf(l1 - m) : 0.f);
#pragma unroll
    for (int off = 16; off > 0; off >>= 1)
        s += __shfl_xor_sync(0xffffffffu, s, off);
    float lse = m + logf(s);

    float* op = out + (size_t)n * F_OUT;
    op[jA] = l0 - lse;
    if (jB < F_OUT) op[jB] = l1 - lse;
}

// ---------------------------------------------------------------------------
extern "C" void kernel_launch(void* const* d_in, const int* in_sizes, int n_in,
                              void* d_out, int out_size) {
    const float* x  = (const float*)d_in[0];
    const void*  ei = d_in[1];
    const float* W1 = (const float*)d_in[2];
    const float* b1 = (const float*)d_in[3];
    const float* W2 = (const float*)d_in[4];
    const float* b2 = (const float*)d_in[5];
    float* out = (float*)d_out;

    k_zero_detect<<<196, 1024>>>((const long long*)ei);
    k_count<<<6250, 256>>>(ei);
    k_scan<<<(N_NODES + 1023) / 1024, 1024>>>();
    k_fill<<<6250, 256>>>(ei);
    k_gemm1<<<(N_NODES + 255) / 256, 256>>>(x, W1);
    k_gather1<<<N_NODES / 8, 256>>>(b1);                // 100000 % 8 == 0
    k_gather2_final<<<N_NODES / 8, 256>>>(W2, b2, out);
}

// round 5
// speedup vs baseline: 1.4474x; 1.0361x over previous
#include <cuda_runtime.h>
#include <math.h>

#define N_NODES 100000
#define N_EDGES 3200000
#define F_IN    256
#define F_HID   16
#define F_OUT   40

// ---- static scratch (no allocations allowed; zero-initialized at load) ----
// Invariant maintained across calls: g_cnt == 0 and g_base == 0 on entry
// (restored by k_scan / k_fill after last use each call).
__device__ float g_hs  [N_NODES * F_HID];  // pass-1 gather source (dinv * xW1)
__device__ float g_hs2 [N_NODES * F_HID];  // pass-2 gather source
__device__ float g_dinv[N_NODES];
__device__ int   g_cnt [N_NODES];          // in-degree scratch (zero on entry)
__device__ int   g_fill[N_NODES];          // cursor; scan sets = rowp, fill -> row end
__device__ int   g_rowp[N_NODES];          // absolute row start in g_csr
__device__ int   g_csr [N_EDGES];          // src ids grouped by dst
__device__ int   g_base;                   // global CSR offset counter (zero on entry)

// ---------------------------------------------------------------------------
// Inline edge-index dtype detection (per block, no global dependency).
// int64 data: first 8 values in [0, N_NODES). int32 node-id data
// reinterpreted as int64 passes only if 8 independent high words are all
// zero: P ~= (1e-5)^8. Deterministic given the input.
// ---------------------------------------------------------------------------
__device__ __forceinline__ int detect_is64_block(const void* ei) {
    __shared__ int s_is64;
    if (threadIdx.x == 0) {
        const long long* p = (const long long*)ei;
        int ok = 1;
#pragma unroll
        for (int j = 0; j < 8; j++) {
            long long v = p[j];
            if (v < 0 || v >= (long long)N_NODES) ok = 0;
        }
        s_is64 = ok;
    }
    __syncthreads();
    return s_is64;
}

__device__ __forceinline__ int edge_at(const void* ei, int is64, long long pos) {
    if (is64) return (int)((const long long*)ei)[pos];
    return ((const int*)ei)[pos];
}

// ---------------------------------------------------------------------------
// In-degree count (scalar int atomics, spread addresses -> near LSU floor)
// ---------------------------------------------------------------------------
__global__ void k_count(const void* __restrict__ ei) {
    int is64 = detect_is64_block(ei);
    int stride = gridDim.x * 256;
    for (int e = blockIdx.x * 256 + threadIdx.x; e < N_EDGES; e += stride) {
        int d = edge_at(ei, is64, (long long)N_EDGES + e);
        atomicAdd(&g_cnt[d], 1);
    }
}

// ---------------------------------------------------------------------------
// Exclusive scan (warp-shuffle within 1024-thr block, block base via
// atomicAdd on g_base). Writes rowp AND seeds the fill cursor = rowp, so
// k_fill's atomic returns absolute slots (no rowp load per edge).
// Also: dinv = rsqrt(cnt+1), and re-zeroes g_cnt (restores invariant).
// ---------------------------------------------------------------------------
__global__ void k_scan() {
    __shared__ int wtot[32];
    __shared__ int sbase;
    int tid  = threadIdx.x;
    int lane = tid & 31, wid = tid >> 5;
    int gid  = blockIdx.x * 1024 + tid;

    int v = (gid < N_NODES) ? g_cnt[gid] : 0;
    int x = v;
#pragma unroll
    for (int off = 1; off < 32; off <<= 1) {
        int t = __shfl_up_sync(0xffffffffu, x, off);
        if (lane >= off) x += t;
    }
    if (lane == 31) wtot[wid] = x;
    __syncthreads();
    if (wid == 0) {
        int w = wtot[lane];
        int y = w;
#pragma unroll
        for (int off = 1; off < 32; off <<= 1) {
            int t = __shfl_up_sync(0xffffffffu, y, off);
            if (lane >= off) y += t;
        }
        wtot[lane] = y - w;                             // exclusive warp offsets
        if (lane == 31) sbase = atomicAdd(&g_base, y);  // block total -> base
    }
    __syncthreads();
    if (gid < N_NODES) {
        int rp = sbase + wtot[wid] + (x - v);
        g_rowp[gid] = rp;
        g_fill[gid] = rp;                    // seed cursor with row start
        g_dinv[gid] = rsqrtf((float)(v + 1));
        g_cnt[gid]  = 0;                     // restore invariant for next call
    }
}

// ---------------------------------------------------------------------------
// CSR fill: slot = atomicAdd(&fill[d],1) is ABSOLUTE; csr[slot] = src.
// After this kernel, g_fill[n] == row end (used as `re` by the gathers).
// Also restores g_base = 0 for the next call.
// ---------------------------------------------------------------------------
__global__ void k_fill(const void* __restrict__ ei) {
    int is64 = detect_is64_block(ei);
    if (blockIdx.x == 0 && threadIdx.x == 0) g_base = 0;  // scan already done
    int stride = gridDim.x * 256;
    for (int e = blockIdx.x * 256 + threadIdx.x; e < N_EDGES; e += stride) {
        int s = edge_at(ei, is64, e);
        int d = edge_at(ei, is64, (long long)N_EDGES + e);
        int slot = atomicAdd(&g_fill[d], 1);
        g_csr[slot] = s;
    }
}

// ---------------------------------------------------------------------------
// Layer-1 GEMM: hs[i,:] = dinv[i] * (x[i,:] @ W1).
// One thread per node; x staged through shared (17-padded), W1 broadcast LDS.
// ---------------------------------------------------------------------------
__global__ void k_gemm1(const float* __restrict__ x, const float* __restrict__ W1) {
    __shared__ float W1s[F_IN * F_HID];      // 16 KB
    __shared__ float xs[256][17];            // 17.4 KB, padded
    int tid = threadIdx.x;
    for (int i = tid; i < F_IN * F_HID; i += 256) W1s[i] = W1[i];

    int node0 = blockIdx.x * 256;
    int node  = node0 + tid;
    float acc[F_HID];
#pragma unroll
    for (int j = 0; j < F_HID; j++) acc[j] = 0.f;
    __syncthreads();

    for (int kc = 0; kc < F_IN; kc += 16) {
#pragma unroll
        for (int r = 0; r < 4; r++) {
            int i  = tid + r * 256;
            int n  = i >> 2, c4 = i & 3;
            float4 v = make_float4(0.f, 0.f, 0.f, 0.f);
            if (node0 + n < N_NODES)
                v = *(const float4*)(x + (size_t)(node0 + n) * F_IN + kc + c4 * 4);
            xs[n][c4 * 4 + 0] = v.x; xs[n][c4 * 4 + 1] = v.y;
            xs[n][c4 * 4 + 2] = v.z; xs[n][c4 * 4 + 3] = v.w;
        }
        __syncthreads();
#pragma unroll
        for (int c = 0; c < 16; c++) {
            float xv = xs[tid][c];
            const float4* wr = (const float4*)(W1s + (kc + c) * F_HID);
            float4 w0 = wr[0], w1 = wr[1], w2 = wr[2], w3 = wr[3];
            acc[0]  = fmaf(xv, w0.x, acc[0]);  acc[1]  = fmaf(xv, w0.y, acc[1]);
            acc[2]  = fmaf(xv, w0.z, acc[2]);  acc[3]  = fmaf(xv, w0.w, acc[3]);
            acc[4]  = fmaf(xv, w1.x, acc[4]);  acc[5]  = fmaf(xv, w1.y, acc[5]);
            acc[6]  = fmaf(xv, w1.z, acc[6]);  acc[7]  = fmaf(xv, w1.w, acc[7]);
            acc[8]  = fmaf(xv, w2.x, acc[8]);  acc[9]  = fmaf(xv, w2.y, acc[9]);
            acc[10] = fmaf(xv, w2.z, acc[10]); acc[11] = fmaf(xv, w2.w, acc[11]);
            acc[12] = fmaf(xv, w3.x, acc[12]); acc[13] = fmaf(xv, w3.y, acc[13]);
            acc[14] = fmaf(xv, w3.z, acc[14]); acc[15] = fmaf(xv, w3.w, acc[15]);
        }
        __syncthreads();
    }

    if (node < N_NODES) {
        float di = g_dinv[node];
#pragma unroll
        for (int j = 0; j < F_HID; j++)
            g_hs[node * F_HID + j] = di * acc[j];
    }
}

// ---------------------------------------------------------------------------
// Vectorized warp gather: lane l -> edge slot (l>>2), quad q = l&3 loads a
// float4 of the source row. One LDG.128 warp instr covers 8 edges; 2-deep
// unroll keeps ~8 loads in flight. After the xor-reduction all lanes hold
// the full sum for their quad q.
// ---------------------------------------------------------------------------
__device__ __forceinline__ float4 warp_gather(const float4* __restrict__ src4,
                                              const int* __restrict__ csr,
                                              int rs, int re, int eo, int q) {
    float4 a0 = make_float4(0.f, 0.f, 0.f, 0.f);
    float4 a1 = make_float4(0.f, 0.f, 0.f, 0.f);
    for (int base = rs; base < re; base += 16) {
        int i0 = base + eo, i1 = base + 8 + eo;
        if (i0 < re) {
            int s = __ldg(&csr[i0]);
            float4 v = src4[(size_t)s * 4 + q];
            a0.x += v.x; a0.y += v.y; a0.z += v.z; a0.w += v.w;
        }
        if (i1 < re) {
            int s = __ldg(&csr[i1]);
            float4 v = src4[(size_t)s * 4 + q];
            a1.x += v.x; a1.y += v.y; a1.z += v.z; a1.w += v.w;
        }
    }
    a0.x += a1.x; a0.y += a1.y; a0.z += a1.z; a0.w += a1.w;
#pragma unroll
    for (int off = 4; off < 32; off <<= 1) {
        a0.x += __shfl_xor_sync(0xffffffffu, a0.x, off);
        a0.y += __shfl_xor_sync(0xffffffffu, a0.y, off);
        a0.z += __shfl_xor_sync(0xffffffffu, a0.z, off);
        a0.w += __shfl_xor_sync(0xffffffffu, a0.w, off);
    }
    return a0;
}

// ---------------------------------------------------------------------------
// Gather pass 1 + fused mid: hs2 = dinv * relu(dinv*(sum + self) + b1)
// Row bounds: rs = rowp[n], re = fill[n] (fill == row end after k_fill).
// ---------------------------------------------------------------------------
__global__ void k_gather1(const float* __restrict__ b1) {
    int tid = threadIdx.x, lane = tid & 31;
    int n = blockIdx.x * 8 + (tid >> 5);      // grid sized so n < N_NODES always
    int eo = lane >> 2, q = lane & 3;
    int rs = g_rowp[n], re = g_fill[n];

    float4 a = warp_gather((const float4*)g_hs, g_csr, rs, re, eo, q);

    float4 sv = ((const float4*)g_hs)[(size_t)n * 4 + q];
    float di = g_dinv[n];
    float4 b = *(const float4*)(b1 + q * 4);
    float4 r;
    r.x = fmaxf(fmaf(di, a.x + sv.x, b.x), 0.f) * di;
    r.y = fmaxf(fmaf(di, a.y + sv.y, b.y), 0.f) * di;
    r.z = fmaxf(fmaf(di, a.z + sv.z, b.z), 0.f) * di;
    r.w = fmaxf(fmaf(di, a.w + sv.w, b.w), 0.f) * di;
    if (lane < 4) ((float4*)g_hs2)[(size_t)n * 4 + lane] = r;  // lane l has q=l
}

// ---------------------------------------------------------------------------
// Gather pass 2 fused with GEMM2 + log_softmax (warp per node).
// ---------------------------------------------------------------------------
__global__ void k_gather2_final(const float* __restrict__ W2,
                                const float* __restrict__ b2,
                                float* __restrict__ out) {
    __shared__ float W2s[F_HID * F_OUT];
    __shared__ float b2s[F_OUT];
    int tid = threadIdx.x;
    for (int i = tid; i < F_HID * F_OUT; i += 256) W2s[i] = W2[i];
    if (tid < F_OUT) b2s[tid] = b2[tid];
    __syncthreads();

    int lane = tid & 31;
    int n = blockIdx.x * 8 + (tid >> 5);
    int eo = lane >> 2, q = lane & 3;
    int rs = g_rowp[n], re = g_fill[n];

    float4 a = warp_gather((const float4*)g_hs2, g_csr, rs, re, eo, q);

    float4 sv = ((const float4*)g_hs2)[(size_t)n * 4 + q];
    float di = g_dinv[n];
    float4 av;                                 // features q*4..q*4+3
    av.x = di * (a.x + sv.x); av.y = di * (a.y + sv.y);
    av.z = di * (a.z + sv.z); av.w = di * (a.w + sv.w);

    // logits: lane handles jA = lane; lanes 0-7 also jB = lane + 32
    int jA = lane, jB = lane + 32;
    float l0 = b2s[jA];
    float l1 = (jB < F_OUT) ? b2s[jB] : -3.0e38f;
#pragma unroll
    for (int kq = 0; kq < 4; kq++) {           // lane kq holds quad kq
        float c0 = __shfl_sync(0xffffffffu, av.x, kq);
        float c1 = __shfl_sync(0xffffffffu, av.y, kq);
        float c2 = __shfl_sync(0xffffffffu, av.z, kq);
        float c3 = __shfl_sync(0xffffffffu, av.w, kq);
        const float* w = W2s + (kq * 4) * F_OUT;
        l0 = fmaf(c0, w[jA],             l0);
        l0 = fmaf(c1, w[F_OUT + jA],     l0);
        l0 = fmaf(c2, w[2 * F_OUT + jA], l0);
        l0 = fmaf(c3, w[3 * F_OUT + jA], l0);
        if (jB < F_OUT) {
            l1 = fmaf(c0, w[jB],             l1);
            l1 = fmaf(c1, w[F_OUT + jB],     l1);
            l1 = fmaf(c2, w[2 * F_OUT + jB], l1);
            l1 = fmaf(c3, w[3 * F_OUT + jB], l1);
        }
    }

    // log_softmax over 40 values spread across the warp
    float m = fmaxf(l0, l1);
#pragma unroll
    for (int off = 16; off > 0; off >>= 1)
        m = fmaxf(m, __shfl_xor_sync(0xffffffffu, m, off));
    float s = expf(l0 - m) + ((jB < F_OUT) ? expf(l1 - m) : 0.f);
#pragma unroll
    for (int off = 16; off > 0; off >>= 1)
        s += __shfl_xor_sync(0xffffffffu, s, off);
    float lse = m + logf(s);

    float* op = out + (size_t)n * F_OUT;
    op[jA] = l0 - lse;
    if (jB < F_OUT) op[jB] = l1 - lse;
}

// ---------------------------------------------------------------------------
extern "C" void kernel_launch(void* const* d_in, const int* in_sizes, int n_in,
                              void* d_out, int out_size) {
    const float* x  = (const float*)d_in[0];
    const void*  ei = d_in[1];
    const float* W1 = (const float*)d_in[2];
    const float* b1 = (const float*)d_in[3];
    const float* W2 = (const float*)d_in[4];
    const float* b2 = (const float*)d_in[5];
    float* out = (float*)d_out;

    k_count<<<6250, 256>>>(ei);
    k_scan<<<(N_NODES + 1023) / 1024, 1024>>>();
    k_fill<<<6250, 256>>>(ei);
    k_gemm1<<<(N_NODES + 255) / 256, 256>>>(x, W1);
    k_gather1<<<N_NODES / 8, 256>>>(b1);                // 100000 % 8 == 0
    k_gather2_final<<<N_NODES / 8, 256>>>(W2, b2, out);
}

// round 6
// speedup vs baseline: 1.5451x; 1.0675x over previous
#include <cuda_runtime.h>
#include <math.h>

#define N_NODES 100000
#define N_EDGES 3200000
#define F_IN    256
#define F_HID   16
#define F_OUT   40

// ---- static scratch (no allocations allowed; zero-initialized at load) ----
// Invariant maintained across calls: g_cnt == 0 and g_base == 0 on entry
// (restored by k_scan / k_fill after last use each call).
__device__ float g_hs  [N_NODES * F_HID];  // pass-1 gather source (dinv * xW1)
__device__ float g_hs2 [N_NODES * F_HID];  // pass-2 gather source
__device__ float g_dinv[N_NODES];
__device__ int   g_cnt [N_NODES];          // in-degree scratch (zero on entry)
__device__ int   g_fill[N_NODES];          // cursor; scan sets = rowp, fill -> row end
__device__ int   g_rowp[N_NODES];          // absolute row start in g_csr
__device__ int   g_csr [N_EDGES];          // src ids grouped by dst
__device__ int   g_base;                   // global CSR offset counter (zero on entry)

// ---------------------------------------------------------------------------
// Inline edge-index dtype detection (per block, no global dependency).
// ---------------------------------------------------------------------------
__device__ __forceinline__ int detect_is64_block(const void* ei) {
    __shared__ int s_is64;
    if (threadIdx.x == 0) {
        const long long* p = (const long long*)ei;
        int ok = 1;
#pragma unroll
        for (int j = 0; j < 8; j++) {
            long long v = p[j];
            if (v < 0 || v >= (long long)N_NODES) ok = 0;
        }
        s_is64 = ok;
    }
    __syncthreads();
    return s_is64;
}

__device__ __forceinline__ int edge_at(const void* ei, int is64, long long pos) {
    if (is64) return (int)((const long long*)ei)[pos];
    return ((const int*)ei)[pos];
}

// ---------------------------------------------------------------------------
// In-degree count
// ---------------------------------------------------------------------------
__global__ void k_count(const void* __restrict__ ei) {
    int is64 = detect_is64_block(ei);
    int stride = gridDim.x * 256;
    for (int e = blockIdx.x * 256 + threadIdx.x; e < N_EDGES; e += stride) {
        int d = edge_at(ei, is64, (long long)N_EDGES + e);
        atomicAdd(&g_cnt[d], 1);
    }
}

// ---------------------------------------------------------------------------
// Exclusive scan; seeds fill cursor = rowp; dinv; re-zeroes g_cnt.
// ---------------------------------------------------------------------------
__global__ void k_scan() {
    __shared__ int wtot[32];
    __shared__ int sbase;
    int tid  = threadIdx.x;
    int lane = tid & 31, wid = tid >> 5;
    int gid  = blockIdx.x * 1024 + tid;

    int v = (gid < N_NODES) ? g_cnt[gid] : 0;
    int x = v;
#pragma unroll
    for (int off = 1; off < 32; off <<= 1) {
        int t = __shfl_up_sync(0xffffffffu, x, off);
        if (lane >= off) x += t;
    }
    if (lane == 31) wtot[wid] = x;
    __syncthreads();
    if (wid == 0) {
        int w = wtot[lane];
        int y = w;
#pragma unroll
        for (int off = 1; off < 32; off <<= 1) {
            int t = __shfl_up_sync(0xffffffffu, y, off);
            if (lane >= off) y += t;
        }
        wtot[lane] = y - w;
        if (lane == 31) sbase = atomicAdd(&g_base, y);
    }
    __syncthreads();
    if (gid < N_NODES) {
        int rp = sbase + wtot[wid] + (x - v);
        g_rowp[gid] = rp;
        g_fill[gid] = rp;
        g_dinv[gid] = rsqrtf((float)(v + 1));
        g_cnt[gid]  = 0;
    }
}

// ---------------------------------------------------------------------------
// CSR fill: slot = atomicAdd(&fill[d],1) is ABSOLUTE. fill[n] -> row end.
// ---------------------------------------------------------------------------
__global__ void k_fill(const void* __restrict__ ei) {
    int is64 = detect_is64_block(ei);
    if (blockIdx.x == 0 && threadIdx.x == 0) g_base = 0;
    int stride = gridDim.x * 256;
    for (int e = blockIdx.x * 256 + threadIdx.x; e < N_EDGES; e += stride) {
        int s = edge_at(ei, is64, e);
        int d = edge_at(ei, is64, (long long)N_EDGES + e);
        int slot = atomicAdd(&g_fill[d], 1);
        g_csr[slot] = s;
    }
}

// ---------------------------------------------------------------------------
// Layer-1 GEMM (rewritten): hs[i,:] = dinv[i] * (x[i,:] @ W1).
// 128 threads/block, 256 nodes/block (2 nodes per thread -> W1 LDS amortized),
// register-prefetch pipeline hides the x-tile DRAM latency under compute.
// xs padded to 17 -> conflict-free column reads.
// ---------------------------------------------------------------------------
__global__ void __launch_bounds__(128)
k_gemm1(const float* __restrict__ x, const float* __restrict__ W1) {
    __shared__ float W1s[F_IN * F_HID];      // 16 KB
    __shared__ float xs[256][17];            // 17.4 KB

    int tid = threadIdx.x;
    int node0 = blockIdx.x * 256;

    for (int i = tid; i < F_IN * F_HID; i += 128) W1s[i] = W1[i];

    float accA[F_HID], accB[F_HID];
#pragma unroll
    for (int j = 0; j < F_HID; j++) { accA[j] = 0.f; accB[j] = 0.f; }

    // prefetch chunk 0: 256 rows x 16 cols = 1024 float4, 8 per thread
    float4 pr[8];
#pragma unroll
    for (int r = 0; r < 8; r++) {
        int i = tid + r * 128;
        int n = i >> 2, c4 = i & 3;
        pr[r] = (node0 + n < N_NODES)
              ? *(const float4*)(x + (size_t)(node0 + n) * F_IN + c4 * 4)
              : make_float4(0.f, 0.f, 0.f, 0.f);
    }

    for (int kc = 0; kc < F_IN; kc += 16) {
        // store staged chunk
#pragma unroll
        for (int r = 0; r < 8; r++) {
            int i = tid + r * 128;
            int n = i >> 2, c4 = i & 3;
            xs[n][c4 * 4 + 0] = pr[r].x; xs[n][c4 * 4 + 1] = pr[r].y;
            xs[n][c4 * 4 + 2] = pr[r].z; xs[n][c4 * 4 + 3] = pr[r].w;
        }
        __syncthreads();

        // prefetch next chunk (overlaps the compute below)
        if (kc + 16 < F_IN) {
#pragma unroll
            for (int r = 0; r < 8; r++) {
                int i = tid + r * 128;
                int n = i >> 2, c4 = i & 3;
                pr[r] = (node0 + n < N_NODES)
                      ? *(const float4*)(x + (size_t)(node0 + n) * F_IN + kc + 16 + c4 * 4)
                      : make_float4(0.f, 0.f, 0.f, 0.f);
            }
        }

#pragma unroll
        for (int c = 0; c < 16; c++) {
            float xa = xs[tid][c];
            float xb = xs[tid + 128][c];
            const float4* wr = (const float4*)(W1s + (kc + c) * F_HID);
            float4 w0 = wr[0], w1 = wr[1], w2 = wr[2], w3 = wr[3];
            accA[0]  = fmaf(xa, w0.x, accA[0]);  accB[0]  = fmaf(xb, w0.x, accB[0]);
            accA[1]  = fmaf(xa, w0.y, accA[1]);  accB[1]  = fmaf(xb, w0.y, accB[1]);
            accA[2]  = fmaf(xa, w0.z, accA[2]);  accB[2]  = fmaf(xb, w0.z, accB[2]);
            accA[3]  = fmaf(xa, w0.w, accA[3]);  accB[3]  = fmaf(xb, w0.w, accB[3]);
            accA[4]  = fmaf(xa, w1.x, accA[4]);  accB[4]  = fmaf(xb, w1.x, accB[4]);
            accA[5]  = fmaf(xa, w1.y, accA[5]);  accB[5]  = fmaf(xb, w1.y, accB[5]);
            accA[6]  = fmaf(xa, w1.z, accA[6]);  accB[6]  = fmaf(xb, w1.z, accB[6]);
            accA[7]  = fmaf(xa, w1.w, accA[7]);  accB[7]  = fmaf(xb, w1.w, accB[7]);
            accA[8]  = fmaf(xa, w2.x, accA[8]);  accB[8]  = fmaf(xb, w2.x, accB[8]);
            accA[9]  = fmaf(xa, w2.y, accA[9]);  accB[9]  = fmaf(xb, w2.y, accB[9]);
            accA[10] = fmaf(xa, w2.z, accA[10]); accB[10] = fmaf(xb, w2.z, accB[10]);
            accA[11] = fmaf(xa, w2.w, accA[11]); accB[11] = fmaf(xb, w2.w, accB[11]);
            accA[12] = fmaf(xa, w3.x, accA[12]); accB[12] = fmaf(xb, w3.x, accB[12]);
            accA[13] = fmaf(xa, w3.y, accA[13]); accB[13] = fmaf(xb, w3.y, accB[13]);
            accA[14] = fmaf(xa, w3.z, accA[14]); accB[14] = fmaf(xb, w3.z, accB[14]);
            accA[15] = fmaf(xa, w3.w, accA[15]); accB[15] = fmaf(xb, w3.w, accB[15]);
        }
        __syncthreads();
    }

    int nodeA = node0 + tid, nodeB = node0 + 128 + tid;
    if (nodeA < N_NODES) {
        float di = g_dinv[nodeA];
#pragma unroll
        for (int j = 0; j < F_HID; j++)
            g_hs[nodeA * F_HID + j] = di * accA[j];
    }
    if (nodeB < N_NODES) {
        float di = g_dinv[nodeB];
#pragma unroll
        for (int j = 0; j < F_HID; j++)
            g_hs[nodeB * F_HID + j] = di * accB[j];
    }
}

// ---------------------------------------------------------------------------
// Vectorized warp gather (unchanged).
// ---------------------------------------------------------------------------
__device__ __forceinline__ float4 warp_gather(const float4* __restrict__ src4,
                                              const int* __restrict__ csr,
                                              int rs, int re, int eo, int q) {
    float4 a0 = make_float4(0.f, 0.f, 0.f, 0.f);
    float4 a1 = make_float4(0.f, 0.f, 0.f, 0.f);
    for (int base = rs; base < re; base += 16) {
        int i0 = base + eo, i1 = base + 8 + eo;
        if (i0 < re) {
            int s = __ldg(&csr[i0]);
            float4 v = src4[(size_t)s * 4 + q];
            a0.x += v.x; a0.y += v.y; a0.z += v.z; a0.w += v.w;
        }
        if (i1 < re) {
            int s = __ldg(&csr[i1]);
            float4 v = src4[(size_t)s * 4 + q];
            a1.x += v.x; a1.y += v.y; a1.z += v.z; a1.w += v.w;
        }
    }
    a0.x += a1.x; a0.y += a1.y; a0.z += a1.z; a0.w += a1.w;
#pragma unroll
    for (int off = 4; off < 32; off <<= 1) {
        a0.x += __shfl_xor_sync(0xffffffffu, a0.x, off);
        a0.y += __shfl_xor_sync(0xffffffffu, a0.y, off);
        a0.z += __shfl_xor_sync(0xffffffffu, a0.z, off);
        a0.w += __shfl_xor_sync(0xffffffffu, a0.w, off);
    }
    return a0;
}

// ---------------------------------------------------------------------------
// Gather pass 1 + fused mid
// ---------------------------------------------------------------------------
__global__ void k_gather1(const float* __restrict__ b1) {
    int tid = threadIdx.x, lane = tid & 31;
    int n = blockIdx.x * 8 + (tid >> 5);
    int eo = lane >> 2, q = lane & 3;
    int rs = g_rowp[n], re = g_fill[n];

    float4 a = warp_gather((const float4*)g_hs, g_csr, rs, re, eo, q);

    float4 sv = ((const float4*)g_hs)[(size_t)n * 4 + q];
    float di = g_dinv[n];
    float4 b = *(const float4*)(b1 + q * 4);
    float4 r;
    r.x = fmaxf(fmaf(di, a.x + sv.x, b.x), 0.f) * di;
    r.y = fmaxf(fmaf(di, a.y + sv.y, b.y), 0.f) * di;
    r.z = fmaxf(fmaf(di, a.z + sv.z, b.z), 0.f) * di;
    r.w = fmaxf(fmaf(di, a.w + sv.w, b.w), 0.f) * di;
    if (lane < 4) ((float4*)g_hs2)[(size_t)n * 4 + lane] = r;
}

// ---------------------------------------------------------------------------
// Gather pass 2 fused with GEMM2 + log_softmax
// ---------------------------------------------------------------------------
__global__ void k_gather2_final(const float* __restrict__ W2,
                                const float* __restrict__ b2,
                                float* __restrict__ out) {
    __shared__ float W2s[F_HID * F_OUT];
    __shared__ float b2s[F_OUT];
    int tid = threadIdx.x;
    for (int i = tid; i < F_HID * F_OUT; i += 256) W2s[i] = W2[i];
    if (tid < F_OUT) b2s[tid] = b2[tid];
    __syncthreads();

    int lane = tid & 31;
    int n = blockIdx.x * 8 + (tid >> 5);
    int eo = lane >> 2, q = lane & 3;
    int rs = g_rowp[n], re = g_fill[n];

    float4 a = warp_gather((const float4*)g_hs2, g_csr, rs, re, eo, q);

    float4 sv = ((const float4*)g_hs2)[(size_t)n * 4 + q];
    float di = g_dinv[n];
    float4 av;
    av.x = di * (a.x + sv.x); av.y = di * (a.y + sv.y);
    av.z = di * (a.z + sv.z); av.w = di * (a.w + sv.w);

    int jA = lane, jB = lane + 32;
    float l0 = b2s[jA];
    float l1 = (jB < F_OUT) ? b2s[jB] : -3.0e38f;
#pragma unroll
    for (int kq = 0; kq < 4; kq++) {
        float c0 = __shfl_sync(0xffffffffu, av.x, kq);
        float c1 = __shfl_sync(0xffffffffu, av.y, kq);
        float c2 = __shfl_sync(0xffffffffu, av.z, kq);
        float c3 = __shfl_sync(0xffffffffu, av.w, kq);
        const float* w = W2s + (kq * 4) * F_OUT;
        l0 = fmaf(c0, w[jA],             l0);
        l0 = fmaf(c1, w[F_OUT + jA],     l0);
        l0 = fmaf(c2, w[2 * F_OUT + jA], l0);
        l0 = fmaf(c3, w[3 * F_OUT + jA], l0);
        if (jB < F_OUT) {
            l1 = fmaf(c0, w[jB],             l1);
            l1 = fmaf(c1, w[F_OUT + jB],     l1);
            l1 = fmaf(c2, w[2 * F_OUT + jB], l1);
            l1 = fmaf(c3, w[3 * F_OUT + jB], l1);
        }
    }

    float m = fmaxf(l0, l1);
#pragma unroll
    for (int off = 16; off > 0; off >>= 1)
        m = fmaxf(m, __shfl_xor_sync(0xffffffffu, m, off));
    float s = expf(l0 - m) + ((jB < F_OUT) ? expf(l1 - m) : 0.f);
#pragma unroll
    for (int off = 16; off > 0; off >>= 1)
        s += __shfl_xor_sync(0xffffffffu, s, off);
    float lse = m + logf(s);

    float* op = out + (size_t)n * F_OUT;
    op[jA] = l0 - lse;
    if (jB < F_OUT) op[jB] = l1 - lse;
}

// ---------------------------------------------------------------------------
extern "C" void kernel_launch(void* const* d_in, const int* in_sizes, int n_in,
                              void* d_out, int out_size) {
    const float* x  = (const float*)d_in[0];
    const void*  ei = d_in[1];
    const float* W1 = (const float*)d_in[2];
    const float* b1 = (const float*)d_in[3];
    const float* W2 = (const float*)d_in[4];
    const float* b2 = (const float*)d_in[5];
    float* out = (float*)d_out;

    k_count<<<6250, 256>>>(ei);
    k_scan<<<(N_NODES + 1023) / 1024, 1024>>>();
    k_fill<<<6250, 256>>>(ei);
    k_gemm1<<<(N_NODES + 255) / 256, 128>>>(x, W1);     // 256 nodes/block
    k_gather1<<<N_NODES / 8, 256>>>(b1);
    k_gather2_final<<<N_NODES / 8, 256>>>(W2, b2, out);
}

// round 8
// speedup vs baseline: 1.5589x; 1.0090x over previous
#include <cuda_runtime.h>
#include <math.h>

#define N_NODES 100000
#define N_EDGES 3200000
#define F_IN    256
#define F_HID   16
#define F_OUT   40

typedef unsigned long long u64;

// ---- static scratch (no allocations allowed; zero-initialized at load) ----
// Invariant maintained across calls: g_cnt == 0 and g_base == 0 on entry
// (restored by k_scan / k_fill after last use each call).
__device__ float g_hs  [N_NODES * F_HID];  // pass-1 gather source (dinv * xW1)
__device__ float g_hs2 [N_NODES * F_HID];  // pass-2 gather source
__device__ float g_dinv[N_NODES];
__device__ int   g_cnt [N_NODES];          // in-degree scratch (zero on entry)
__device__ int   g_fill[N_NODES];          // cursor; scan sets = rowp, fill -> row end
__device__ int   g_rowp[N_NODES];          // absolute row start in g_csr
__device__ int   g_csr [N_EDGES];          // src ids grouped by dst
__device__ int   g_base;                   // global CSR offset counter (zero on entry)

// ---- packed f32x2 helpers (Blackwell sm_100a) ----
__device__ __forceinline__ u64 pack2(float lo, float hi) {
    u64 r; asm("mov.b64 %0, {%1, %2};" : "=l"(r) : "f"(lo), "f"(hi)); return r;
}
__device__ __forceinline__ void fma2(u64& d, u64 a, u64 b) {
    asm("fma.rn.f32x2 %0, %1, %2, %0;" : "+l"(d) : "l"(a), "l"(b));
}
__device__ __forceinline__ void mul2(u64& d, u64 a, u64 b) {
    asm("mul.rn.f32x2 %0, %1, %2;" : "=l"(d) : "l"(a), "l"(b));
}

// ---------------------------------------------------------------------------
// Inline edge-index dtype detection (per block, no global dependency).
// int64 data: first 8 values in [0, N_NODES). int32 node-id data
// reinterpreted as int64 passes only if 8 independent high words are all
// zero: P ~= (1e-5)^8. Deterministic given the input.
// ---------------------------------------------------------------------------
__device__ __forceinline__ int detect_is64_block(const void* ei) {
    __shared__ int s_is64;
    if (threadIdx.x == 0) {
        const long long* p = (const long long*)ei;
        int ok = 1;
#pragma unroll
        for (int j = 0; j < 8; j++) {
            long long v = p[j];
            if (v < 0 || v >= (long long)N_NODES) ok = 0;
        }
        s_is64 = ok;
    }
    __syncthreads();
    return s_is64;
}

__device__ __forceinline__ int edge_at(const void* ei, int is64, long long pos) {
    if (is64) return (int)((const long long*)ei)[pos];
    return ((const int*)ei)[pos];
}

// ---------------------------------------------------------------------------
// In-degree count
// ---------------------------------------------------------------------------
__global__ void k_count(const void* __restrict__ ei) {
    int is64 = detect_is64_block(ei);
    int stride = gridDim.x * 256;
    for (int e = blockIdx.x * 256 + threadIdx.x; e < N_EDGES; e += stride) {
        int d = edge_at(ei, is64, (long long)N_EDGES + e);
        atomicAdd(&g_cnt[d], 1);
    }
}

// ---------------------------------------------------------------------------
// Exclusive scan; seeds fill cursor = rowp; dinv; re-zeroes g_cnt.
// ---------------------------------------------------------------------------
__global__ void k_scan() {
    __shared__ int wtot[32];
    __shared__ int sbase;
    int tid  = threadIdx.x;
    int lane = tid & 31, wid = tid >> 5;
    int gid  = blockIdx.x * 1024 + tid;

    int v = (gid < N_NODES) ? g_cnt[gid] : 0;
    int x = v;
#pragma unroll
    for (int off = 1; off < 32; off <<= 1) {
        int t = __shfl_up_sync(0xffffffffu, x, off);
        if (lane >= off) x += t;
    }
    if (lane == 31) wtot[wid] = x;
    __syncthreads();
    if (wid == 0) {
        int w = wtot[lane];
        int y = w;
#pragma unroll
        for (int off = 1; off < 32; off <<= 1) {
            int t = __shfl_up_sync(0xffffffffu, y, off);
            if (lane >= off) y += t;
        }
        wtot[lane] = y - w;
        if (lane == 31) sbase = atomicAdd(&g_base, y);
    }
    __syncthreads();
    if (gid < N_NODES) {
        int rp = sbase + wtot[wid] + (x - v);
        g_rowp[gid] = rp;
        g_fill[gid] = rp;
        g_dinv[gid] = rsqrtf((float)(v + 1));
        g_cnt[gid]  = 0;
    }
}

// ---------------------------------------------------------------------------
// CSR fill: slot = atomicAdd(&fill[d],1) is ABSOLUTE. fill[n] -> row end.
// ---------------------------------------------------------------------------
__global__ void k_fill(const void* __restrict__ ei) {
    int is64 = detect_is64_block(ei);
    if (blockIdx.x == 0 && threadIdx.x == 0) g_base = 0;
    int stride = gridDim.x * 256;
    for (int e = blockIdx.x * 256 + threadIdx.x; e < N_EDGES; e += stride) {
        int s = edge_at(ei, is64, e);
        int d = edge_at(ei, is64, (long long)N_EDGES + e);
        int slot = atomicAdd(&g_fill[d], 1);
        g_csr[slot] = s;
    }
}

// ---------------------------------------------------------------------------
// Layer-1 GEMM v3: hs[i,:] = dinv[i] * (x[i,:] @ W1).
// 128 threads/block, 2 nodes/thread. NO shared x, NO per-chunk barriers:
// each thread streams its own two x rows via LDG.128 (full-sector reads),
// W1 broadcast from shared, math in packed f32x2 (halves FMA instructions).
// Without barriers ptxas can pipeline next-chunk loads under current FFMA2s.
// ---------------------------------------------------------------------------
__global__ void __launch_bounds__(128)
k_gemm1(const float* __restrict__ x, const float* __restrict__ W1) {
    __shared__ float W1s[F_IN * F_HID];      // 16 KB
    int tid = threadIdx.x;
    {
        const float4* src = (const float4*)W1;
        float4* dst = (float4*)W1s;
#pragma unroll
        for (int r = 0; r < 8; r++) dst[tid + r * 128] = src[tid + r * 128];
    }
    __syncthreads();

    int nodeA = blockIdx.x * 256 + tid;
    int nodeB = nodeA + 128;
    int vB = nodeB < N_NODES;                 // nodeA always < N_NODES (391*256 grid)
    const float4* xA = (const float4*)(x + (size_t)nodeA * F_IN);
    const float4* xB = (const float4*)(x + (size_t)(vB ? nodeB : 0) * F_IN);

    u64 accA[8], accB[8];
#pragma unroll
    for (int j = 0; j < 8; j++) { accA[j] = 0ull; accB[j] = 0ull; }

    const float* wp = W1s;
    for (int kc = 0; kc < F_IN; kc += 16) {
        float ar[16], br[16];
#pragma unroll
        for (int r = 0; r < 4; r++) {
            ((float4*)ar)[r] = xA[r];
            ((float4*)br)[r] = xB[r];
        }
        xA += 4; xB += 4;
#pragma unroll
        for (int c = 0; c < 16; c++) {
            // W1 row (kc+c): 16 floats = 8 packed f32x2, read directly as u64
            const ulonglong2* wq = (const ulonglong2*)(wp + c * F_HID);
            ulonglong2 w0 = wq[0], w1 = wq[1], w2 = wq[2], w3 = wq[3];
            u64 xa = pack2(ar[c], ar[c]);
            u64 xb = pack2(br[c], br[c]);
            fma2(accA[0], xa, w0.x); fma2(accB[0], xb, w0.x);
            fma2(accA[1], xa, w0.y); fma2(accB[1], xb, w0.y);
            fma2(accA[2], xa, w1.x); fma2(accB[2], xb, w1.x);
            fma2(accA[3], xa, w1.y); fma2(accB[3], xb, w1.y);
            fma2(accA[4], xa, w2.x); fma2(accB[4], xb, w2.x);
            fma2(accA[5], xa, w2.y); fma2(accB[5], xb, w2.y);
            fma2(accA[6], xa, w3.x); fma2(accB[6], xb, w3.x);
            fma2(accA[7], xa, w3.y); fma2(accB[7], xb, w3.y);
        }
        wp += 16 * F_HID;
    }

    {
        u64 dA = pack2(g_dinv[nodeA], g_dinv[nodeA]);
        ulonglong2* row = (ulonglong2*)(g_hs + (size_t)nodeA * F_HID);
#pragma unroll
        for (int p = 0; p < 4; p++) {
            ulonglong2 o;
            mul2(o.x, accA[2 * p], dA);
            mul2(o.y, accA[2 * p + 1], dA);
            row[p] = o;
        }
    }
    if (vB) {
        u64 dB = pack2(g_dinv[nodeB], g_dinv[nodeB]);
        ulonglong2* row = (ulonglong2*)(g_hs + (size_t)nodeB * F_HID);
#pragma unroll
        for (int p = 0; p < 4; p++) {
            ulonglong2 o;
            mul2(o.x, accB[2 * p], dB);
            mul2(o.y, accB[2 * p + 1], dB);
            row[p] = o;
        }
    }
}

// ---------------------------------------------------------------------------
// Vectorized warp gather: lane l -> edge slot (l>>2), quad q = l&3 loads a
// float4 of the source row. One LDG.128 warp instr covers 8 edges; 2-deep
// unroll keeps ~8 loads in flight. After the xor-reduction all lanes hold
// the full sum for their quad q.
// ---------------------------------------------------------------------------
__device__ __forceinline__ float4 warp_gather(const float4* __restrict__ src4,
                                              const int* __restrict__ csr,
                                              int rs, int re, int eo, int q) {
    float4 a0 = make_float4(0.f, 0.f, 0.f, 0.f);
    float4 a1 = make_float4(0.f, 0.f, 0.f, 0.f);
    for (int base = rs; base < re; base += 16) {
        int i0 = base + eo, i1 = base + 8 + eo;
        if (i0 < re) {
            int s = __ldg(&csr[i0]);
            float4 v = src4[(size_t)s * 4 + q];
            a0.x += v.x; a0.y += v.y; a0.z += v.z; a0.w += v.w;
        }
        if (i1 < re) {
            int s = __ldg(&csr[i1]);
            float4 v = src4[(size_t)s * 4 + q];
            a1.x += v.x; a1.y += v.y; a1.z += v.z; a1.w += v.w;
        }
    }
    a0.x += a1.x; a0.y += a1.y; a0.z += a1.z; a0.w += a1.w;
#pragma unroll
    for (int off = 4; off < 32; off <<= 1) {
        a0.x += __shfl_xor_sync(0xffffffffu, a0.x, off);
        a0.y += __shfl_xor_sync(0xffffffffu, a0.y, off);
        a0.z += __shfl_xor_sync(0xffffffffu, a0.z, off);
        a0.w += __shfl_xor_sync(0xffffffffu, a0.w, off);
    }
    return a0;
}

// ---------------------------------------------------------------------------
// Gather pass 1 + fused mid: hs2 = dinv * relu(dinv*(sum + self) + b1)
// ---------------------------------------------------------------------------
__global__ void k_gather1(const float* __restrict__ b1) {
    int tid = threadIdx.x, lane = tid & 31;
    int n = blockIdx.x * 8 + (tid >> 5);
    int eo = lane >> 2, q = lane & 3;
    int rs = g_rowp[n], re = g_fill[n];

    float4 a = warp_gather((const float4*)g_hs, g_csr, rs, re, eo, q);

    float4 sv = ((const float4*)g_hs)[(size_t)n * 4 + q];
    float di = g_dinv[n];
    float4 b = *(const float4*)(b1 + q * 4);
    float4 r;
    r.x = fmaxf(fmaf(di, a.x + sv.x, b.x), 0.f) * di;
    r.y = fmaxf(fmaf(di, a.y + sv.y, b.y), 0.f) * di;
    r.z = fmaxf(fmaf(di, a.z + sv.z, b.z), 0.f) * di;
    r.w = fmaxf(fmaf(di, a.w + sv.w, b.w), 0.f) * di;
    if (lane < 4) ((float4*)g_hs2)[(size_t)n * 4 + lane] = r;
}

// ---------------------------------------------------------------------------
// Gather pass 2 fused with GEMM2 + log_softmax
// ---------------------------------------------------------------------------
__global__ void k_gather2_final(const float* __restrict__ W2,
                                const float* __restrict__ b2,
                                float* __restrict__ out) {
    __shared__ float W2s[F_HID * F_OUT];
    __shared__ float b2s[F_OUT];
    int tid = threadIdx.x;
    for (int i = tid; i < F_HID * F_OUT; i += 256) W2s[i] = W2[i];
    if (tid < F_OUT) b2s[tid] = b2[tid];
    __syncthreads();

    int lane = tid & 31;
    int n = blockIdx.x * 8 + (tid >> 5);
    int eo = lane >> 2, q = lane & 3;
    int rs = g_rowp[n], re = g_fill[n];

    float4 a = warp_gather((const float4*)g_hs2, g_csr, rs, re, eo, q);

    float4 sv = ((const float4*)g_hs2)[(size_t)n * 4 + q];
    float di = g_dinv[n];
    float4 av;
    av.x = di * (a.x + sv.x); av.y = di * (a.y + sv.y);
    av.z = di * (a.z + sv.z); av.w = di * (a.w + sv.w);

    int jA = lane, jB = lane + 32;
    float l0 = b2s[jA];
    float l1 = (jB < F_OUT) ? b2s[jB] : -3.0e38f;
#pragma unroll
    for (int kq = 0; kq < 4; kq++) {
        float c0 = __shfl_sync(0xffffffffu, av.x, kq);
        float c1 = __shfl_sync(0xffffffffu, av.y, kq);
        float c2 = __shfl_sync(0xffffffffu, av.z, kq);
        float c3 = __shfl_sync(0xffffffffu, av.w, kq);
        const float* w = W2s + (kq * 4) * F_OUT;
        l0 = fmaf(c0, w[jA],             l0);
        l0 = fmaf(c1, w[F_OUT + jA],     l0);
        l0 = fmaf(c2, w[2 * F_OUT + jA], l0);
        l0 = fmaf(c3, w[3 * F_OUT + jA], l0);
        if (jB < F_OUT) {
            l1 = fmaf(c0, w[jB],             l1);
            l1 = fmaf(c1, w[F_OUT + jB],     l1);
            l1 = fmaf(c2, w[2 * F_OUT + jB], l1);
            l1 = fmaf(c3, w[3 * F_OUT + jB], l1);
        }
    }

    float m = fmaxf(l0, l1);
#pragma unroll
    for (int off = 16; off > 0; off >>= 1)
        m = fmaxf(m, __shfl_xor_sync(0xffffffffu, m, off));
    float s = expf(l0 - m) + ((jB < F_OUT) ? expf(l1 - m) : 0.f);
#pragma unroll
    for (int off = 16; off > 0; off >>= 1)
        s += __shfl_xor_sync(0xffffffffu, s, off);
    float lse = m + logf(s);

    float* op = out + (size_t)n * F_OUT;
    op[jA] = l0 - lse;
    if (jB < F_OUT) op[jB] = l1 - lse;
}

// ---------------------------------------------------------------------------
extern "C" void kernel_launch(void* const* d_in, const int* in_sizes, int n_in,
                              void* d_out, int out_size) {
    const float* x  = (const float*)d_in[0];
    const void*  ei = d_in[1];
    const float* W1 = (const float*)d_in[2];
    const float* b1 = (const float*)d_in[3];
    const float* W2 = (const float*)d_in[4];
    const float* b2 = (const float*)d_in[5];
    float* out = (float*)d_out;

    k_count<<<6250, 256>>>(ei);
    k_scan<<<(N_NODES + 1023) / 1024, 1024>>>();
    k_fill<<<6250, 256>>>(ei);
    k_gemm1<<<(N_NODES + 255) / 256, 128>>>(x, W1);     // 256 nodes/block
    k_gather1<<<N_NODES / 8, 256>>>(b1);
    k_gather2_final<<<N_NODES / 8, 256>>>(W2, b2, out);
}